// round 16
// baseline (speedup 1.0000x reference)
#include <cuda_runtime.h>
#include <cuda_fp16.h>
#include <cstdint>

#define B_ 16
#define N_ 196
#define C_ 768
#define H_ 512
#define O_ 128

// ---------------- device scratch (static, no allocs) ----------------
// A panel: [z][b][row 0..255][k 0..767] fp16. Rows >= 196 are NEVER written:
// __device__ globals are zero-initialized, fp16 zero rows -> relu(0)=0, colsum unaffected.
__device__ __align__(256) __half g_A[2u*16*256*768];
// B panel (W transposed): [z][h 0..511][k 0..767] fp16
__device__ __align__(256) __half g_B[2u*512*768];
// partial column sums: [z][b][mt 4][h 512]
__device__ float g_part[2*16*4*512];
// per-batch completion counters (start 0; last arriver resets to 0 -> replay-safe)
__device__ unsigned g_cnt[B_];

// ---------------- helpers ----------------
__device__ __forceinline__ uint32_t smem_u32(const void* p) {
    uint32_t a;
    asm("{ .reg .u64 t; cvta.to.shared.u64 t, %1; cvt.u32.u64 %0, t; }" : "=r"(a) : "l"(p));
    return a;
}
__device__ __forceinline__ void cp16(uint32_t dst, const void* src) {
    asm volatile("cp.async.cg.shared.global [%0], [%1], 16;" :: "r"(dst), "l"(src) : "memory");
}
__device__ __forceinline__ void ldsm_x4(uint32_t* r, uint32_t addr) {
    asm volatile("ldmatrix.sync.aligned.m8n8.x4.shared.b16 {%0,%1,%2,%3}, [%4];"
                 : "=r"(r[0]), "=r"(r[1]), "=r"(r[2]), "=r"(r[3]) : "r"(addr));
}
__device__ __forceinline__ void mma_f32acc(float* d, const uint32_t* a, const uint32_t* b) {
    asm volatile("mma.sync.aligned.m16n8k16.row.col.f32.f16.f16.f32 "
                 "{%0,%1,%2,%3}, {%4,%5,%6,%7}, {%8,%9}, {%0,%1,%2,%3};"
                 : "+f"(d[0]), "+f"(d[1]), "+f"(d[2]), "+f"(d[3])
                 : "r"(a[0]), "r"(a[1]), "r"(a[2]), "r"(a[3]), "r"(b[0]), "r"(b[1]));
}
__device__ __forceinline__ uint32_t h2_bits(__half a, __half b) {
    __half2 t = __halves2half2(a, b);
    return *reinterpret_cast<uint32_t*>(&t);
}

// ---------------- fused pack: A panel (196 real rows only) + B panel ----------------
// blocks [0,2352): pack_A ; [2352,2544): pack_B
#define PA_BLOCKS 2352

__global__ void pack_all(const float* __restrict__ x1, const float* __restrict__ x2,
                         const float* __restrict__ W1, const float* __restrict__ W2)
{
    __shared__ float ts[64][65];
    int bx = blockIdx.x;
    int tid = threadIdx.x;

    if (bx < PA_BLOCKS) {
        // ---- pack A: one 8-elem unit per thread, only the 196 real rows ----
        int u = bx * 256 + tid;
        int kg = u % 96;  int t = u / 96;
        int row = t % 196; int bb = t / 196;
        int b = bb & 15, z = bb >> 4;
        const float* x = z ? x2 : x1;
        const float4* src = reinterpret_cast<const float4*>(
            x + ((size_t)b * N_ + row) * C_ + kg * 8);
        float4 v0 = src[0], v1 = src[1];
        uint4 hv;
        hv.x = h2_bits(__float2half_rn(v0.x), __float2half_rn(v0.y));
        hv.y = h2_bits(__float2half_rn(v0.z), __float2half_rn(v0.w));
        hv.z = h2_bits(__float2half_rn(v1.x), __float2half_rn(v1.y));
        hv.w = h2_bits(__float2half_rn(v1.z), __float2half_rn(v1.w));
        size_t off = ((size_t)(z * 16 + b) * 256 + row) * 768 + kg * 8;
        *reinterpret_cast<uint4*>(g_A + off) = hv;
    } else {
        // ---- pack B: W [C,H] fp32 -> transposed fp16 [H,C] ----
        int beta = bx - PA_BLOCKS;
        int kc = beta % 12, hb = (beta / 12) & 7, z = beta / 96;
        const float* W = z ? W2 : W1;
        int c0 = kc * 64, h0 = hb * 64;
        #pragma unroll
        for (int i = 0; i < 16; i++) {
            int idx = tid + i * 256;
            int cl = idx >> 6, hl = idx & 63;
            ts[cl][hl] = W[(size_t)(c0 + cl) * H_ + h0 + hl];
        }
        __syncthreads();
        #pragma unroll
        for (int j = 0; j < 2; j++) {
            int unit = tid + j * 256;
            int row = unit >> 3, kg = unit & 7;
            uint32_t hi[4];
            #pragma unroll
            for (int i = 0; i < 4; i++) {
                hi[i] = h2_bits(__float2half_rn(ts[kg * 8 + 2*i][row]),
                                __float2half_rn(ts[kg * 8 + 2*i + 1][row]));
            }
            size_t off = ((size_t)z * 512 + h0 + row) * 768 + c0 + kg * 8;
            *reinterpret_cast<uint4*>(g_B + off) = make_uint4(hi[0], hi[1], hi[2], hi[3]);
        }
    }
}

// ---------------- GEMM + fused finalize ----------------
// BK=64, 2-stage ping-pong, one sync/stage (R12/R14-proven). NEW: fragment
// double-buffering — kk+1's ldsm issue before kk's MMAs, hiding smem latency.
#define ROWB 144
#define B_OFF (64*ROWB)                   // A: 64 rows x 144B = 9216
#define STAGE_BYTES (B_OFF + 256*ROWB)    // 46080
#define SMEM_TOTAL (2*STAGE_BYTES)        // 92160

__device__ __forceinline__ void load_stage(
    uint32_t base, int kbase, int tid, const __half* A, const __half* Bp)
{
    #pragma unroll
    for (int i = 0; i < 2; i++) {                 // A: 512 16B units (64 rows x 8 quads)
        int u = tid + i * 256;
        int q = u & 7, row = u >> 3;
        cp16(base + row * ROWB + q * 16, A + (size_t)row * 768 + kbase + q * 8);
    }
    #pragma unroll
    for (int i = 0; i < 8; i++) {                 // B: 2048 16B units (256 rows x 8 quads)
        int u = tid + i * 256;
        int q = u & 7, row = u >> 3;
        cp16(base + B_OFF + row * ROWB + q * 16, Bp + (size_t)row * 768 + kbase + q * 8);
    }
    asm volatile("cp.async.commit_group;" ::: "memory");
}

__global__ __launch_bounds__(256, 2) void gemm_hmma(
    const float* __restrict__ Wp, const float* __restrict__ bp, float* __restrict__ out)
{
    extern __shared__ char sm[];
    uint32_t sb = smem_u32(sm);
    int tid = threadIdx.x, wid = tid >> 5, lane = tid & 31;
    int z = blockIdx.z, b = blockIdx.y;
    int mt = blockIdx.x >> 1, nt = blockIdx.x & 1;
    int wm = wid & 1, wn = wid >> 1;

    const __half* A  = g_A + ((size_t)(z * 16 + b) * 256 + mt * 64) * 768;
    const __half* Bp = g_B + ((size_t)z * 512 + nt * 256) * 768;

    float acc[2][8][4];
    #pragma unroll
    for (int mf = 0; mf < 2; mf++)
        #pragma unroll
        for (int nf = 0; nf < 8; nf++)
            #pragma unroll
            for (int d = 0; d < 4; d++) acc[mf][nf][d] = 0.f;

    uint32_t aoff[2];
    #pragma unroll
    for (int mf = 0; mf < 2; mf++) {
        int row = wm * 32 + mf * 16 + (lane & 7) + ((lane >> 3) & 1) * 8;
        aoff[mf] = row * ROWB + (lane >> 4) * 16;
    }
    uint32_t boff[4];
    #pragma unroll
    for (int np = 0; np < 4; np++) {
        int row = wn * 64 + np * 16 + (lane & 7) + (lane >> 4) * 8;
        boff[np] = row * ROWB + ((lane >> 3) & 1) * 16;
    }

    load_stage(sb, 0, tid, A, Bp);

    for (int s = 0; s < 12; s++) {
        asm volatile("cp.async.wait_group 0;" ::: "memory");
        __syncthreads();
        // Issue loads for s+1 AFTER the barrier (buffer (s+1)&1 last read in s-1).
        if (s < 11)
            load_stage(sb + ((s + 1) & 1) * STAGE_BYTES, (s + 1) * 64, tid, A, Bp);

        uint32_t abase = sb + (s & 1) * STAGE_BYTES;
        uint32_t bbase = abase + B_OFF;

        // ---- fragment double-buffer: preload kk=0, then overlap kk+1 loads with kk MMAs
        uint32_t ah[2][2][4], bh[2][4][4];
        #pragma unroll
        for (int mf = 0; mf < 2; mf++)
            ldsm_x4(ah[0][mf], abase + aoff[mf]);
        #pragma unroll
        for (int np = 0; np < 4; np++)
            ldsm_x4(bh[0][np], bbase + boff[np]);

        #pragma unroll
        for (int kk = 0; kk < 4; kk++) {
            const int cur = kk & 1, nxt = cur ^ 1;
            if (kk < 3) {
                #pragma unroll
                for (int mf = 0; mf < 2; mf++)
                    ldsm_x4(ah[nxt][mf], abase + aoff[mf] + (kk + 1) * 32);
                #pragma unroll
                for (int np = 0; np < 4; np++)
                    ldsm_x4(bh[nxt][np], bbase + boff[np] + (kk + 1) * 32);
            }
            #pragma unroll
            for (int mf = 0; mf < 2; mf++)
                #pragma unroll
                for (int nf = 0; nf < 8; nf++) {
                    int np = nf >> 1, hh = (nf & 1) * 2;
                    uint32_t bb[2] = { bh[cur][np][hh], bh[cur][np][hh + 1] };
                    mma_f32acc(acc[mf][nf], ah[cur][mf], bb);
                }
        }
    }

    // ---------------- epilogue: relu + column sums ----------------
    float* red = (float*)sm;     // [2][256] floats (buffer 0; all warps passed stage-11 barrier)
    #pragma unroll
    for (int nf = 0; nf < 8; nf++) {
        float s0 = 0.f, s1 = 0.f;
        #pragma unroll
        for (int mf = 0; mf < 2; mf++) {
            s0 += fmaxf(acc[mf][nf][0], 0.f) + fmaxf(acc[mf][nf][2], 0.f);
            s1 += fmaxf(acc[mf][nf][1], 0.f) + fmaxf(acc[mf][nf][3], 0.f);
        }
        #pragma unroll
        for (int off = 4; off < 32; off <<= 1) {
            s0 += __shfl_xor_sync(0xffffffff, s0, off);
            s1 += __shfl_xor_sync(0xffffffff, s1, off);
        }
        if (lane < 4) {
            red[wm * 256 + wn * 64 + nf * 8 + lane * 2]     = s0;
            red[wm * 256 + wn * 64 + nf * 8 + lane * 2 + 1] = s1;
        }
    }
    __syncthreads();
    float part = red[tid] + red[256 + tid];
    g_part[((size_t)(z * 16 + b) * 4 + mt) * 512 + nt * 256 + tid] = part;

    // ---------------- fused finalize: last CTA of batch b computes out[b,:] ----------------
    __shared__ unsigned s_ticket;
    __threadfence();              // make this CTA's g_part stores globally visible
    __syncthreads();              // all threads' stores done before the count
    if (tid == 0) s_ticket = atomicAdd(&g_cnt[b], 1u);
    __syncthreads();
    if (s_ticket == 15u) {        // 16 CTAs per b (2z x 4mt x 2nt) -> we are last
        if (tid == 0) g_cnt[b] = 0u;    // reset for next graph replay
        float* sp = (float*)sm;         // [512] products + [512..1024) reduction
        #pragma unroll
        for (int j = tid; j < 512; j += 256) {
            float c1 = 0.f, c2 = 0.f;
            #pragma unroll
            for (int mtq = 0; mtq < 4; mtq++) {
                c1 += g_part[((size_t)(0 * 16 + b) * 4 + mtq) * 512 + j];
                c2 += g_part[((size_t)(1 * 16 + b) * 4 + mtq) * 512 + j];
            }
            sp[j] = c1 * c2;
        }
        __syncthreads();
        int o = tid & 127, half = tid >> 7;
        float a2 = 0.f;
        #pragma unroll 16
        for (int i = 0; i < 256; i++) {
            int h = half * 256 + i;
            a2 = fmaf(sp[h], Wp[(size_t)h * O_ + o], a2);
        }
        float* racc = sp + 512;
        racc[tid] = a2;
        __syncthreads();
        if (tid < 128)
            out[b * O_ + tid] = racc[tid] + racc[128 + tid] + bp[tid] * 38416.f;
    }
}

// ---------------- launch ----------------
extern "C" void kernel_launch(void* const* d_in, const int* in_sizes, int n_in,
                              void* d_out, int out_size) {
    const float* x1 = (const float*)d_in[0];
    const float* x2 = (const float*)d_in[1];
    const float* W1 = (const float*)d_in[2];
    const float* W2 = (const float*)d_in[3];
    const float* Wp = (const float*)d_in[4];
    const float* bp = (const float*)d_in[5];
    float* out = (float*)d_out;

    cudaFuncSetAttribute(gemm_hmma, cudaFuncAttributeMaxDynamicSharedMemorySize, SMEM_TOTAL);

    pack_all<<<PA_BLOCKS + 192, 256>>>(x1, x2, W1, W2);
    gemm_hmma<<<dim3(8, 16, 2), 256, SMEM_TOTAL>>>(Wp, bp, out);
}

// round 17
// speedup vs baseline: 1.0591x; 1.0591x over previous
#include <cuda_runtime.h>
#include <cuda_fp16.h>
#include <cstdint>

#define B_ 16
#define N_ 196
#define C_ 768
#define H_ 512
#define O_ 128

// ---------------- device scratch (static, no allocs) ----------------
// A panel: [z][b][row 0..255][k 0..767] fp16. Rows >= 196 are NEVER written:
// __device__ globals are zero-initialized, fp16 zero rows -> relu(0)=0, colsum unaffected.
__device__ __align__(256) __half g_A[2u*16*256*768];
// B panel (W transposed): [z][h 0..511][k 0..767] fp16
__device__ __align__(256) __half g_B[2u*512*768];
// partial column sums: [z][b][mt 2][h 512]
__device__ float g_part[2*16*2*512];
// per-batch completion counters (start 0; last arriver resets to 0 -> replay-safe)
__device__ unsigned g_cnt[B_];

// ---------------- helpers ----------------
__device__ __forceinline__ uint32_t smem_u32(const void* p) {
    uint32_t a;
    asm("{ .reg .u64 t; cvta.to.shared.u64 t, %1; cvt.u32.u64 %0, t; }" : "=r"(a) : "l"(p));
    return a;
}
__device__ __forceinline__ void cp16(uint32_t dst, const void* src) {
    asm volatile("cp.async.cg.shared.global [%0], [%1], 16;" :: "r"(dst), "l"(src) : "memory");
}
__device__ __forceinline__ void ldsm_x4(uint32_t* r, uint32_t addr) {
    asm volatile("ldmatrix.sync.aligned.m8n8.x4.shared.b16 {%0,%1,%2,%3}, [%4];"
                 : "=r"(r[0]), "=r"(r[1]), "=r"(r[2]), "=r"(r[3]) : "r"(addr));
}
__device__ __forceinline__ void mma_f32acc(float* d, const uint32_t* a, const uint32_t* b) {
    asm volatile("mma.sync.aligned.m16n8k16.row.col.f32.f16.f16.f32 "
                 "{%0,%1,%2,%3}, {%4,%5,%6,%7}, {%8,%9}, {%0,%1,%2,%3};"
                 : "+f"(d[0]), "+f"(d[1]), "+f"(d[2]), "+f"(d[3])
                 : "r"(a[0]), "r"(a[1]), "r"(a[2]), "r"(a[3]), "r"(b[0]), "r"(b[1]));
}
__device__ __forceinline__ uint32_t h2_bits(__half a, __half b) {
    __half2 t = __halves2half2(a, b);
    return *reinterpret_cast<uint32_t*>(&t);
}

// ---------------- fused pack: A panel (196 real rows only) + B panel ----------------
// blocks [0,2352): pack_A ; [2352,2544): pack_B
#define PA_BLOCKS 2352

__global__ void pack_all(const float* __restrict__ x1, const float* __restrict__ x2,
                         const float* __restrict__ W1, const float* __restrict__ W2)
{
    __shared__ float ts[64][65];
    int bx = blockIdx.x;
    int tid = threadIdx.x;

    if (bx < PA_BLOCKS) {
        // ---- pack A: one 8-elem unit per thread, only the 196 real rows ----
        int u = bx * 256 + tid;
        int kg = u % 96;  int t = u / 96;
        int row = t % 196; int bb = t / 196;
        int b = bb & 15, z = bb >> 4;
        const float* x = z ? x2 : x1;
        const float4* src = reinterpret_cast<const float4*>(
            x + ((size_t)b * N_ + row) * C_ + kg * 8);
        float4 v0 = src[0], v1 = src[1];
        uint4 hv;
        hv.x = h2_bits(__float2half_rn(v0.x), __float2half_rn(v0.y));
        hv.y = h2_bits(__float2half_rn(v0.z), __float2half_rn(v0.w));
        hv.z = h2_bits(__float2half_rn(v1.x), __float2half_rn(v1.y));
        hv.w = h2_bits(__float2half_rn(v1.z), __float2half_rn(v1.w));
        size_t off = ((size_t)(z * 16 + b) * 256 + row) * 768 + kg * 8;
        *reinterpret_cast<uint4*>(g_A + off) = hv;
    } else {
        // ---- pack B: W [C,H] fp32 -> transposed fp16 [H,C] ----
        int beta = bx - PA_BLOCKS;
        int kc = beta % 12, hb = (beta / 12) & 7, z = beta / 96;
        const float* W = z ? W2 : W1;
        int c0 = kc * 64, h0 = hb * 64;
        #pragma unroll
        for (int i = 0; i < 16; i++) {
            int idx = tid + i * 256;
            int cl = idx >> 6, hl = idx & 63;
            ts[cl][hl] = W[(size_t)(c0 + cl) * H_ + h0 + hl];
        }
        __syncthreads();
        #pragma unroll
        for (int j = 0; j < 2; j++) {
            int unit = tid + j * 256;
            int row = unit >> 3, kg = unit & 7;
            uint32_t hi[4];
            #pragma unroll
            for (int i = 0; i < 4; i++) {
                hi[i] = h2_bits(__float2half_rn(ts[kg * 8 + 2*i][row]),
                                __float2half_rn(ts[kg * 8 + 2*i + 1][row]));
            }
            size_t off = ((size_t)z * 512 + h0 + row) * 768 + c0 + kg * 8;
            *reinterpret_cast<uint4*>(g_B + off) = make_uint4(hi[0], hi[1], hi[2], hi[3]);
        }
    }
}

// ---------------- GEMM + fused finalize ----------------
// Tile M=128, N=128, BK=64, 256 threads (8 warps: wm{0,1} x wn{0..3}, warp m64 x n32).
// 2-stage ping-pong, one sync/stage, loads issued post-barrier (R12/R14/R15-proven).
// Square tiles cut chip L2 traffic 138 -> 100 MB. 256 CTAs, 2 CTAs/SM, single wave.
#define ROWB 144
#define B_OFF (128*ROWB)                  // A: 128 rows x 144B = 18432
#define STAGE_BYTES (2*B_OFF)             // 36864 (A 18432 + B 18432)
#define SMEM_TOTAL (2*STAGE_BYTES)        // 73728

__device__ __forceinline__ void load_stage(
    uint32_t base, int kbase, int tid, const __half* A, const __half* Bp)
{
    #pragma unroll
    for (int i = 0; i < 4; i++) {                 // A: 1024 16B units (128 rows x 8 quads)
        int u = tid + i * 256;
        int q = u & 7, row = u >> 3;
        cp16(base + row * ROWB + q * 16, A + (size_t)row * 768 + kbase + q * 8);
    }
    #pragma unroll
    for (int i = 0; i < 4; i++) {                 // B: 1024 16B units (128 rows x 8 quads)
        int u = tid + i * 256;
        int q = u & 7, row = u >> 3;
        cp16(base + B_OFF + row * ROWB + q * 16, Bp + (size_t)row * 768 + kbase + q * 8);
    }
    asm volatile("cp.async.commit_group;" ::: "memory");
}

__global__ __launch_bounds__(256, 2) void gemm_hmma(
    const float* __restrict__ Wp, const float* __restrict__ bp, float* __restrict__ out)
{
    extern __shared__ char sm[];
    uint32_t sb = smem_u32(sm);
    int tid = threadIdx.x, wid = tid >> 5, lane = tid & 31;
    int z = blockIdx.z, b = blockIdx.y;
    int mt = blockIdx.x >> 2, nt = blockIdx.x & 3;
    int wm = wid & 1, wn = wid >> 1;

    const __half* A  = g_A + ((size_t)(z * 16 + b) * 256 + mt * 128) * 768;
    const __half* Bp = g_B + ((size_t)z * 512 + nt * 128) * 768;

    float acc[4][4][4];          // [mf m16][nf n8][d]
    #pragma unroll
    for (int mf = 0; mf < 4; mf++)
        #pragma unroll
        for (int nf = 0; nf < 4; nf++)
            #pragma unroll
            for (int d = 0; d < 4; d++) acc[mf][nf][d] = 0.f;

    uint32_t aoff[4];
    #pragma unroll
    for (int mf = 0; mf < 4; mf++) {
        int row = wm * 64 + mf * 16 + (lane & 7) + ((lane >> 3) & 1) * 8;
        aoff[mf] = row * ROWB + (lane >> 4) * 16;
    }
    uint32_t boff[2];
    #pragma unroll
    for (int np = 0; np < 2; np++) {
        int row = wn * 32 + np * 16 + (lane & 7) + (lane >> 4) * 8;
        boff[np] = row * ROWB + ((lane >> 3) & 1) * 16;
    }

    load_stage(sb, 0, tid, A, Bp);

    for (int s = 0; s < 12; s++) {
        asm volatile("cp.async.wait_group 0;" ::: "memory");
        __syncthreads();
        // Issue loads for s+1 AFTER the barrier (buffer (s+1)&1 last read in s-1).
        if (s < 11)
            load_stage(sb + ((s + 1) & 1) * STAGE_BYTES, (s + 1) * 64, tid, A, Bp);

        uint32_t abase = sb + (s & 1) * STAGE_BYTES;
        uint32_t bbase = abase + B_OFF;
        #pragma unroll
        for (int kk = 0; kk < 4; kk++) {
            uint32_t ah[4][4], bh[2][4];
            #pragma unroll
            for (int mf = 0; mf < 4; mf++)
                ldsm_x4(ah[mf], abase + aoff[mf] + kk * 32);
            #pragma unroll
            for (int np = 0; np < 2; np++)
                ldsm_x4(bh[np], bbase + boff[np] + kk * 32);
            #pragma unroll
            for (int mf = 0; mf < 4; mf++)
                #pragma unroll
                for (int nf = 0; nf < 4; nf++) {
                    int np = nf >> 1, hh = (nf & 1) * 2;
                    uint32_t bb[2] = { bh[np][hh], bh[np][hh + 1] };
                    mma_f32acc(acc[mf][nf], ah[mf], bb);
                }
        }
    }

    // ---------------- epilogue: relu + column sums ----------------
    float* red = (float*)sm;     // [2][128] floats (buffer 0; all warps passed stage-11 barrier)
    #pragma unroll
    for (int nf = 0; nf < 4; nf++) {
        float s0 = 0.f, s1 = 0.f;
        #pragma unroll
        for (int mf = 0; mf < 4; mf++) {
            s0 += fmaxf(acc[mf][nf][0], 0.f) + fmaxf(acc[mf][nf][2], 0.f);
            s1 += fmaxf(acc[mf][nf][1], 0.f) + fmaxf(acc[mf][nf][3], 0.f);
        }
        #pragma unroll
        for (int off = 4; off < 32; off <<= 1) {
            s0 += __shfl_xor_sync(0xffffffff, s0, off);
            s1 += __shfl_xor_sync(0xffffffff, s1, off);
        }
        if (lane < 4) {
            red[wm * 128 + wn * 32 + nf * 8 + lane * 2]     = s0;
            red[wm * 128 + wn * 32 + nf * 8 + lane * 2 + 1] = s1;
        }
    }
    __syncthreads();
    if (tid < 128) {
        float part = red[tid] + red[128 + tid];
        g_part[((size_t)(z * 16 + b) * 2 + mt) * 512 + nt * 128 + tid] = part;
    }

    // ---------------- fused finalize: last CTA of batch b computes out[b,:] ----------------
    __shared__ unsigned s_ticket;
    __threadfence();              // make this CTA's g_part stores globally visible
    __syncthreads();              // all threads' stores done before the count
    if (tid == 0) s_ticket = atomicAdd(&g_cnt[b], 1u);
    __syncthreads();
    if (s_ticket == 15u) {        // 16 CTAs per b (2z x 2mt x 4nt) -> we are last
        if (tid == 0) g_cnt[b] = 0u;    // reset for next graph replay
        float* sp = (float*)sm;         // [512] products + [512..1024) reduction
        #pragma unroll
        for (int j = tid; j < 512; j += 256) {
            float c1 = 0.f, c2 = 0.f;
            #pragma unroll
            for (int mtq = 0; mtq < 2; mtq++) {
                c1 += g_part[((size_t)(0 * 16 + b) * 2 + mtq) * 512 + j];
                c2 += g_part[((size_t)(1 * 16 + b) * 2 + mtq) * 512 + j];
            }
            sp[j] = c1 * c2;
        }
        __syncthreads();
        int o = tid & 127, half = tid >> 7;
        float a2 = 0.f;
        #pragma unroll 16
        for (int i = 0; i < 256; i++) {
            int h = half * 256 + i;
            a2 = fmaf(sp[h], Wp[(size_t)h * O_ + o], a2);
        }
        float* racc = sp + 512;
        racc[tid] = a2;
        __syncthreads();
        if (tid < 128)
            out[b * O_ + tid] = racc[tid] + racc[128 + tid] + bp[tid] * 38416.f;
    }
}

// ---------------- launch ----------------
extern "C" void kernel_launch(void* const* d_in, const int* in_sizes, int n_in,
                              void* d_out, int out_size) {
    const float* x1 = (const float*)d_in[0];
    const float* x2 = (const float*)d_in[1];
    const float* W1 = (const float*)d_in[2];
    const float* W2 = (const float*)d_in[3];
    const float* Wp = (const float*)d_in[4];
    const float* bp = (const float*)d_in[5];
    float* out = (float*)d_out;

    cudaFuncSetAttribute(gemm_hmma, cudaFuncAttributeMaxDynamicSharedMemorySize, SMEM_TOTAL);

    pack_all<<<PA_BLOCKS + 192, 256>>>(x1, x2, W1, W2);
    gemm_hmma<<<dim3(8, 16, 2), 256, SMEM_TOTAL>>>(Wp, bp, out);
}